// round 7
// baseline (speedup 1.0000x reference)
#include <cuda_runtime.h>
#include <cuda_bf16.h>
#include <cstdint>

#define AN 9216      // N = 96*96
#define HH 96
#define WW 96
#define FD 64
#define PW 98        // padded width
#define PAN (PW*PW)  // padded plane = 9604

// ---------------- scratch (device globals; no allocation allowed) ------------
__device__ float g_h [3*FD*PAN];          // padded extractor hidden
__device__ float g_f [3*FD*AN];           // features f1,f2,f3 (unpadded)
__device__ __nv_bfloat16 g_QT [AN*8];     // [n][8] (pre-scaled by log2e)
__device__ __nv_bfloat16 g_KT1[AN*8];
__device__ __nv_bfloat16 g_KT3[AN*8];
__device__ __nv_bfloat16 g_V1 [AN*FD];    // [key][64]
__device__ __nv_bfloat16 g_V3 [AN*FD];
__device__ float g_oP [4*FD*AN];          // partial O: [pca*2+half][ch][n]
__device__ float g_rsP[4*AN];             // partial rowsums
__device__ float g_fus[FD*PAN];           // padded
__device__ float g_fh [FD*PAN];           // padded

// ---------------- helpers -----------------------------------------------------
__device__ __forceinline__ uint32_t smem_u32(const void* p) {
    uint32_t a;
    asm("{ .reg .u64 t; cvta.to.shared.u64 t, %1; cvt.u32.u64 %0, t; }" : "=r"(a) : "l"(p));
    return a;
}
__device__ __forceinline__ float ex2f(float x) {
    float y;
    asm("ex2.approx.f32 %0, %1;" : "=f"(y) : "f"(x));
    return y;
}
__device__ __forceinline__ void mma_s8(float c[4], uint32_t a0, uint32_t a1, uint32_t b) {
    asm("mma.sync.aligned.m16n8k8.row.col.f32.bf16.bf16.f32 "
        "{%0,%1,%2,%3},{%4,%5},{%6},{%0,%1,%2,%3};"
        : "+f"(c[0]), "+f"(c[1]), "+f"(c[2]), "+f"(c[3])
        : "r"(a0), "r"(a1), "r"(b));
}
__device__ __forceinline__ void mma_pv(float c[4], const uint32_t a[4], uint32_t b0, uint32_t b1) {
    asm("mma.sync.aligned.m16n8k16.row.col.f32.bf16.bf16.f32 "
        "{%0,%1,%2,%3},{%4,%5,%6,%7},{%8,%9},{%0,%1,%2,%3};"
        : "+f"(c[0]), "+f"(c[1]), "+f"(c[2]), "+f"(c[3])
        : "r"(a[0]), "r"(a[1]), "r"(a[2]), "r"(a[3]), "r"(b0), "r"(b1));
}
__device__ __forceinline__ void ldsm4t(uint32_t r[4], uint32_t addr) {
    asm volatile("ldmatrix.sync.aligned.m8n8.x4.trans.shared.b16 {%0,%1,%2,%3}, [%4];"
                 : "=r"(r[0]), "=r"(r[1]), "=r"(r[2]), "=r"(r[3]) : "r"(addr));
}
__device__ __forceinline__ uint32_t pkbf(float lo, float hi) {
    __nv_bfloat162 h2 = __floats2bfloat162_rn(lo, hi);
    return *reinterpret_cast<uint32_t*>(&h2);
}
__device__ __forceinline__ void cpa16(uint32_t dst, const void* src) {
    asm volatile("cp.async.cg.shared.global [%0], [%1], 16;" :: "r"(dst), "l"(src) : "memory");
}
#define CPA_COMMIT() asm volatile("cp.async.commit_group;" ::: "memory")
#define CPA_WAIT0()  asm volatile("cp.async.wait_group 0;" ::: "memory")

// ---------------- zero the pad rings of padded buffers -----------------------
// 320 channel-planes: h(3*64), fus(64), fh(64). Ring = 388 elems/plane.
__global__ void padzero_k(float* h, float* fus, float* fh) {
    const int b = blockIdx.x;
    float* base = (b < 192) ? (h + (long)b * PAN)
                : (b < 256) ? (fus + (long)(b - 192) * PAN)
                            : (fh + (long)(b - 256) * PAN);
    const int t = threadIdx.x;
    if (t < 98)       base[t] = 0.0f;                       // top row
    else if (t < 196) base[97 * PW + (t - 98)] = 0.0f;      // bottom row
    else if (t < 292) base[(t - 196 + 1) * PW] = 0.0f;      // left col
    else if (t < 388) base[(t - 292 + 1) * PW + 97] = 0.0f; // right col
}

// ---------------- conv 3->64 from raw NCHW input, writes PADDED --------------
template<int CPB>
__global__ void convA_k(const float* __restrict__ in0, const float* __restrict__ in1,
                        const float* __restrict__ in2,
                        const float* __restrict__ w, const float* __restrict__ bias,
                        float* __restrict__ out) {
    __shared__ float ws[CPB * 3 * 9];
    const int oc0 = blockIdx.y * CPB;
    for (int i = threadIdx.x; i < CPB * 3 * 9; i += blockDim.x)
        ws[i] = w[oc0 * 3 * 9 + i];
    __syncthreads();

    const int z = blockIdx.z;
    const float* in = (z == 0) ? in0 : (z == 1) ? in1 : in2;
    float* outp = out + (long)z * FD * PAN;

    const int p = blockIdx.x * blockDim.x + threadIdx.x;
    const int y = p / WW, x = p % WW;

    float acc[CPB];
#pragma unroll
    for (int k = 0; k < CPB; k++) acc[k] = bias[oc0 + k];

#pragma unroll
    for (int c = 0; c < 3; c++) {
        float v[9];
#pragma unroll
        for (int dy = 0; dy < 3; dy++) {
            const int yy = y + dy - 1;
#pragma unroll
            for (int dx = 0; dx < 3; dx++) {
                const int xx = x + dx - 1;
                v[dy * 3 + dx] = (yy >= 0 && yy < HH && xx >= 0 && xx < WW)
                                     ? in[c * AN + yy * WW + xx] : 0.0f;
            }
        }
#pragma unroll
        for (int k = 0; k < CPB; k++) {
            const float* wk = ws + k * 27 + c * 9;
#pragma unroll
            for (int j = 0; j < 9; j++) acc[k] += wk[j] * v[j];
        }
    }
#pragma unroll
    for (int k = 0; k < CPB; k++)
        outp[(oc0 + k) * PAN + (y + 1) * PW + (x + 1)] = fmaxf(acc[k], 0.0f);
}

// ---------------- 64->COUT conv from PADDED input, 2x2 px/thread -------------
// TO_PAD: write padded layout (for chained convs); else raw [c][9216].
template<int CPB, bool RELU, bool TO_PAD>
__global__ __launch_bounds__(128) void convP_k(
    const float* __restrict__ in, const float* __restrict__ w,
    const float* __restrict__ bias, float* __restrict__ out) {
    __shared__ float ws[CPB * FD * 9];
    const int oc0 = blockIdx.y * CPB;
    for (int i = threadIdx.x; i < CPB * FD * 9; i += blockDim.x)
        ws[i] = w[oc0 * FD * 9 + i];
    __syncthreads();

    const float* inz  = in + (long)blockIdx.z * FD * PAN;
    float* outp = out + (long)blockIdx.z * FD * AN;

    const int cell = blockIdx.x * blockDim.x + threadIdx.x;   // 0..2303
    const int cx = cell % 48, cy = cell / 48;
    const int x = 2 * cx, y = 2 * cy;

    float acc[CPB][4];
#pragma unroll
    for (int k = 0; k < CPB; k++) {
        const float b = bias[oc0 + k];
#pragma unroll
        for (int j = 0; j < 4; j++) acc[k][j] = b;
    }

    const float* ip = inz + y * PW + x;   // window rows y..y+3, cols x..x+3 (padded)
    for (int c = 0; c < FD; c++) {
        float v[4][4];
#pragma unroll
        for (int r = 0; r < 4; r++)
#pragma unroll
            for (int s = 0; s < 4; s++)
                v[r][s] = ip[r * PW + s];
        ip += PAN;
#pragma unroll
        for (int k = 0; k < CPB; k++) {
            const float* wk = ws + (k * FD + c) * 9;
#pragma unroll
            for (int r = 0; r < 3; r++)
#pragma unroll
                for (int s = 0; s < 3; s++) {
                    const float wv = wk[r * 3 + s];
                    acc[k][0] += wv * v[r][s];
                    acc[k][1] += wv * v[r][s + 1];
                    acc[k][2] += wv * v[r + 1][s];
                    acc[k][3] += wv * v[r + 1][s + 1];
                }
        }
    }

#pragma unroll
    for (int k = 0; k < CPB; k++)
#pragma unroll
        for (int yy = 0; yy < 2; yy++)
#pragma unroll
            for (int xx = 0; xx < 2; xx++) {
                float r = acc[k][yy * 2 + xx];
                if (RELU) r = fmaxf(r, 0.0f);
                if (TO_PAD)
                    outp[(oc0 + k) * PAN + (y + yy + 1) * PW + (x + xx + 1)] = r;
                else
                    outp[(oc0 + k) * AN + (y + yy) * WW + (x + xx)] = r;
            }
}

// ---------------- final conv 64->3 from PADDED input -------------------------
__global__ void convF2_k(const float* __restrict__ in, const float* __restrict__ w,
                         const float* __restrict__ bias, float* __restrict__ out) {
    __shared__ float ws[3 * FD * 9];
    for (int i = threadIdx.x; i < 3 * FD * 9; i += blockDim.x) ws[i] = w[i];
    __syncthreads();
    const int p = blockIdx.x * blockDim.x + threadIdx.x;
    const int y = p / WW, x = p % WW;
    float acc[3] = {bias[0], bias[1], bias[2]};
    const float* ip = in + y * PW + x;
    for (int c = 0; c < FD; c++) {
        float v[9];
#pragma unroll
        for (int r = 0; r < 3; r++)
#pragma unroll
            for (int s = 0; s < 3; s++) v[r * 3 + s] = ip[r * PW + s];
        ip += PAN;
#pragma unroll
        for (int k = 0; k < 3; k++) {
            const float* wk = ws + (k * FD + c) * 9;
#pragma unroll
            for (int j = 0; j < 9; j++) acc[k] += wk[j] * v[j];
        }
    }
#pragma unroll
    for (int k = 0; k < 3; k++) out[k * AN + p] = acc[k];
}

// -------- Q/K1/K3 projections in one launch, 4 threads per pixel -------------
// z: 0 -> Q(f2) scaled by log2e, 1 -> K(f1), 2 -> K(f3). Output bf16 [n][8].
__global__ __launch_bounds__(256) void projT8s_k(
    const float* __restrict__ f, const float* __restrict__ q_w, const float* __restrict__ q_b,
    const float* __restrict__ k_w, const float* __restrict__ k_b,
    __nv_bfloat16* __restrict__ QT, __nv_bfloat16* __restrict__ KT1,
    __nv_bfloat16* __restrict__ KT3) {
    const int z = blockIdx.y;
    const float* in = (z == 0) ? (f + (long)FD * AN) : (z == 1) ? f : (f + 2L * FD * AN);
    const float* w  = (z == 0) ? q_w : k_w;
    const float* b  = (z == 0) ? q_b : k_b;
    __nv_bfloat16* out = (z == 0) ? QT : (z == 1) ? KT1 : KT3;
    const float scale = (z == 0) ? 1.4426950408889634f : 1.0f;   // fold log2e into Q

    __shared__ float ws[8 * FD];
    for (int i = threadIdx.x; i < 8 * FD; i += 256) ws[i] = w[i] * scale;
    __syncthreads();

    const int tid = threadIdx.x;
    const int p   = tid >> 2;          // pixel within block (0..63)
    const int cc  = tid & 3;           // channel chunk
    const int n   = blockIdx.x * 64 + p;

    float acc[8] = {0, 0, 0, 0, 0, 0, 0, 0};
    const int c0 = cc * 16;
#pragma unroll
    for (int c = c0; c < c0 + 16; c++) {
        const float x = in[c * AN + n];
#pragma unroll
        for (int o = 0; o < 8; o++) acc[o] += ws[o * FD + c] * x;
    }
#pragma unroll
    for (int o = 0; o < 8; o++) {
        acc[o] += __shfl_xor_sync(0xFFFFFFFFu, acc[o], 1);
        acc[o] += __shfl_xor_sync(0xFFFFFFFFu, acc[o], 2);
    }
    if (cc == 0) {
        uint32_t pk[4];
#pragma unroll
        for (int i = 0; i < 4; i++)
            pk[i] = pkbf(acc[2 * i] + b[2 * i] * scale, acc[2 * i + 1] + b[2 * i + 1] * scale);
        reinterpret_cast<uint4*>(out)[n] = make_uint4(pk[0], pk[1], pk[2], pk[3]);
    }
}

// ---------------- V projection as tiled GEMM: 64px x 64out per CTA -----------
__global__ __launch_bounds__(256) void projV_k(
    const float* __restrict__ f, const float* __restrict__ w,
    const float* __restrict__ bias,
    __nv_bfloat16* __restrict__ V1, __nv_bfloat16* __restrict__ V3) {
    __shared__ float sin_[FD][64];
    __shared__ float sw[FD * FD];
    __shared__ float sb[FD];
    const int z = blockIdx.y;
    const float* in = z ? (f + 2L * FD * AN) : f;
    __nv_bfloat16* out = z ? V3 : V1;
    const int n0 = blockIdx.x * 64;
    const int tid = threadIdx.x;

    for (int i = tid; i < FD * FD; i += 256) sw[i] = w[i];
    if (tid < FD) sb[tid] = bias[tid];
#pragma unroll
    for (int p = 0; p < 4; p++) {
        const int idx = tid + p * 256;
        const int c = idx >> 4, q = idx & 15;
        *reinterpret_cast<float4*>(&sin_[c][q * 4]) =
            *reinterpret_cast<const float4*>(in + c * AN + n0 + q * 4);
    }
    __syncthreads();

    const int px = tid & 31;
    const int og = tid >> 5;
    float acc[8][2];
#pragma unroll
    for (int o = 0; o < 8; o++) {
        acc[o][0] = sb[og * 8 + o];
        acc[o][1] = acc[o][0];
    }
#pragma unroll
    for (int c = 0; c < FD; c++) {
        const float x0 = sin_[c][px], x1 = sin_[c][px + 32];
#pragma unroll
        for (int o = 0; o < 8; o++) {
            const float wv = sw[(og * 8 + o) * FD + c];
            acc[o][0] += wv * x0;
            acc[o][1] += wv * x1;
        }
    }
    uint32_t pk0[4], pk1[4];
#pragma unroll
    for (int i = 0; i < 4; i++) {
        pk0[i] = pkbf(acc[2 * i][0], acc[2 * i + 1][0]);
        pk1[i] = pkbf(acc[2 * i][1], acc[2 * i + 1][1]);
    }
    *reinterpret_cast<uint4*>(out + (long)(n0 + px) * FD + og * 8) =
        make_uint4(pk0[0], pk0[1], pk0[2], pk0[3]);
    *reinterpret_cast<uint4*>(out + (long)(n0 + px + 32) * FD + og * 8) =
        make_uint4(pk1[0], pk1[1], pk1[2], pk1[3]);
}

// ---------------- mma.sync flash cross-attention, key-split, pipelined -------
// grid (72, pca, key-half). Double-buffered V tile via cp.async; K fragments
// software-prefetched one chunk ahead. Writes UNNORMALIZED partial O + rowsums.
__global__ __launch_bounds__(256, 2) void attn_mma_k(
    const __nv_bfloat16* __restrict__ qt,
    const __nv_bfloat16* __restrict__ kt1, const __nv_bfloat16* __restrict__ v1,
    const __nv_bfloat16* __restrict__ kt3, const __nv_bfloat16* __restrict__ v3,
    float* __restrict__ oP, float* __restrict__ rsP) {

    __shared__ __align__(128) __nv_bfloat16 sv[2][128 * FD];   // 2 x 16 KB V tiles

    const __nv_bfloat16* kt = blockIdx.y ? kt3 : kt1;
    const __nv_bfloat16* v  = blockIdx.y ? v3  : v1;
    const int part = blockIdx.y * 2 + blockIdx.z;
    float* out = oP  + (long)part * FD * AN;
    float* rso = rsP + part * AN;

    const int tid  = threadIdx.x;
    const int wid  = tid >> 5;
    const int lane = tid & 31;
    const int gid  = lane >> 2;      // row group within fragment
    const int tig  = lane & 3;       // thread-in-group
    const int q0   = blockIdx.x * 128;
    const int qb   = q0 + wid * 16;
    const int t0   = blockIdx.z * 36;

    // Q A-fragments (persist across all key tiles)
    const uint32_t qa0 = *reinterpret_cast<const uint32_t*>(qt + (qb + gid) * 8 + tig * 2);
    const uint32_t qa1 = *reinterpret_cast<const uint32_t*>(qt + (qb + 8 + gid) * 8 + tig * 2);

    float o[8][4];
#pragma unroll
    for (int i = 0; i < 8; i++)
#pragma unroll
        for (int j = 0; j < 4; j++) o[i][j] = 0.0f;
    float rs_lo = 0.0f, rs_hi = 0.0f;

    const uint32_t svb = smem_u32(&sv[0][0]);
    const int lm_m = lane >> 3, lm_r = lane & 7;
    const int lm_krow_off = (lm_m & 1) * 8 + lm_r;   // key row within 16-chunk
    const int lm_c16_off  = lm_m >> 1;               // 16B column offset (0 or 1)

    // cp.async V-tile fill: 1 src ptr + fixed offsets (swizzle is p-invariant)
    const int vkey = tid >> 3, vc16 = tid & 7;
    const uint32_t vdst0 = svb + (uint32_t)(vkey * 128 + ((vc16 ^ (vkey & 7)) << 4));
    const __nv_bfloat16* vsrc = v + (size_t)(t0 * 128 + vkey) * FD + vc16 * 8;

    // prologue: fill buffer 0 with tile t0
    cpa16(vdst0,         vsrc);
    cpa16(vdst0 + 4096,  vsrc + 32 * FD);
    cpa16(vdst0 + 8192,  vsrc + 64 * FD);
    cpa16(vdst0 + 12288, vsrc + 96 * FD);
    CPA_COMMIT();
    vsrc += 128 * FD;
    CPA_WAIT0();
    __syncthreads();

    // rolling K pointer + first chunk's fragments
    const __nv_bfloat16* kp = kt + (size_t)(t0 * 128 + gid) * 8;
    uint32_t kbA = *reinterpret_cast<const uint32_t*>(kp + tig * 2);
    uint32_t kbB = *reinterpret_cast<const uint32_t*>(kp + 64 + tig * 2);
    int cc_left = 36 * 8 - 1;   // chunks remaining after the current one

    for (int t = 0; t < 36; t++) {
        // kick off async copy of next V tile into the other buffer
        if (t < 35) {
            const uint32_t d = vdst0 + (uint32_t)(((t + 1) & 1) * 16384);
            cpa16(d,         vsrc);
            cpa16(d + 4096,  vsrc + 32 * FD);
            cpa16(d + 8192,  vsrc + 64 * FD);
            cpa16(d + 12288, vsrc + 96 * FD);
            CPA_COMMIT();
            vsrc += 128 * FD;
        }
        const uint32_t svread = svb + (uint32_t)((t & 1) * 16384);

#pragma unroll
        for (int j = 0; j < 8; j++) {
            float sA[4] = {0, 0, 0, 0}, sB[4] = {0, 0, 0, 0};
            mma_s8(sA, qa0, qa1, kbA);
            mma_s8(sB, qa0, qa1, kbB);

            // prefetch next chunk's K fragments (covers exp/pv section)
            const __nv_bfloat16* kpn = kp + ((cc_left > 0) ? 128 : 0);
            const uint32_t nA = *reinterpret_cast<const uint32_t*>(kpn + tig * 2);
            const uint32_t nB = *reinterpret_cast<const uint32_t*>(kpn + 64 + tig * 2);
            cc_left--;

#pragma unroll
            for (int i = 0; i < 4; i++) { sA[i] = ex2f(sA[i]); sB[i] = ex2f(sB[i]); }
            rs_lo += (sA[0] + sA[1]) + (sB[0] + sB[1]);
            rs_hi += (sA[2] + sA[3]) + (sB[2] + sB[3]);
            uint32_t pa[4];
            pa[0] = pkbf(sA[0], sA[1]);
            pa[1] = pkbf(sA[2], sA[3]);
            pa[2] = pkbf(sB[0], sB[1]);
            pa[3] = pkbf(sB[2], sB[3]);

            const int krow = j * 16 + lm_krow_off;
            const uint32_t rowb = svread + krow * 128;
#pragma unroll
            for (int np = 0; np < 4; np++) {
                const int c16 = np * 2 + lm_c16_off;
                uint32_t vb[4];
                ldsm4t(vb, rowb + ((c16 ^ (krow & 7)) * 16));
                mma_pv(o[2 * np],     pa, vb[0], vb[1]);
                mma_pv(o[2 * np + 1], pa, vb[2], vb[3]);
            }
            kbA = nA; kbB = nB; kp = kpn;
        }

        if (t < 35) CPA_WAIT0();
        __syncthreads();
    }

    rs_lo += __shfl_xor_sync(0xFFFFFFFFu, rs_lo, 1);
    rs_lo += __shfl_xor_sync(0xFFFFFFFFu, rs_lo, 2);
    rs_hi += __shfl_xor_sync(0xFFFFFFFFu, rs_hi, 1);
    rs_hi += __shfl_xor_sync(0xFFFFFFFFu, rs_hi, 2);

    const int row_lo = qb + gid, row_hi = qb + 8 + gid;
    if (tig == 0) { rso[row_lo] = rs_lo; rso[row_hi] = rs_hi; }
#pragma unroll
    for (int nt = 0; nt < 8; nt++) {
        const int ch = nt * 8 + tig * 2;
        out[ch * AN + row_lo]       = o[nt][0];
        out[(ch + 1) * AN + row_lo] = o[nt][1];
        out[ch * AN + row_hi]       = o[nt][2];
        out[(ch + 1) * AN + row_hi] = o[nt][3];
    }
}

// -------- combine key-split partials + normalize + fuse (writes PADDED) ------
__global__ void comb_fuse_k(const float* __restrict__ oP, const float* __restrict__ rsP,
                            const float* __restrict__ f2, float* __restrict__ out) {
    const int n  = blockIdx.x * blockDim.x + threadIdx.x;
    const int ch = blockIdx.y;
    const long i = (long)ch * AN + n;
    const float inv1 = 1.0f / (rsP[n] + rsP[AN + n]);
    const float inv3 = 1.0f / (rsP[2 * AN + n] + rsP[3 * AN + n]);
    const float al1 = (oP[i] + oP[(long)FD * AN + i]) * inv1;
    const float al3 = (oP[2L * FD * AN + i] + oP[3L * FD * AN + i]) * inv3;
    const int y = n / WW, x = n % WW;
    out[(long)ch * PAN + (y + 1) * PW + (x + 1)] =
        (al1 + al3) * (1.0f / 3.0f) + f2[i];
}

// ---------------- launch ------------------------------------------------------
extern "C" void kernel_launch(void* const* d_in, const int* in_sizes, int n_in,
                              void* d_out, int out_size) {
    const float* l1     = (const float*)d_in[0];
    const float* l2     = (const float*)d_in[1];
    const float* l3     = (const float*)d_in[2];
    const float* ext_w1 = (const float*)d_in[3];
    const float* ext_b1 = (const float*)d_in[4];
    const float* ext_w2 = (const float*)d_in[5];
    const float* ext_b2 = (const float*)d_in[6];
    const float* q_w    = (const float*)d_in[7];
    const float* q_b    = (const float*)d_in[8];
    const float* k_w    = (const float*)d_in[9];
    const float* k_b    = (const float*)d_in[10];
    const float* v_w    = (const float*)d_in[11];
    const float* v_b    = (const float*)d_in[12];
    const float* fus_w1 = (const float*)d_in[13];
    const float* fus_b1 = (const float*)d_in[14];
    const float* fus_w2 = (const float*)d_in[15];
    const float* fus_b2 = (const float*)d_in[16];
    float* out = (float*)d_out;

    float *h, *f, *oP, *rsP, *fus, *fh;
    __nv_bfloat16 *QT, *KT1, *KT3, *V1, *V3;
    cudaGetSymbolAddress((void**)&h,   g_h);
    cudaGetSymbolAddress((void**)&f,   g_f);
    cudaGetSymbolAddress((void**)&QT,  g_QT);
    cudaGetSymbolAddress((void**)&KT1, g_KT1);
    cudaGetSymbolAddress((void**)&KT3, g_KT3);
    cudaGetSymbolAddress((void**)&V1,  g_V1);
    cudaGetSymbolAddress((void**)&V3,  g_V3);
    cudaGetSymbolAddress((void**)&oP,  g_oP);
    cudaGetSymbolAddress((void**)&rsP, g_rsP);
    cudaGetSymbolAddress((void**)&fus, g_fus);
    cudaGetSymbolAddress((void**)&fh,  g_fh);

    float* f2 = f + (long)FD * AN;

    // zero pad rings of padded buffers (idempotent, every call)
    padzero_k<<<320, 512>>>(h, fus, fh);

    // feature extraction
    convA_k<8><<<dim3(AN / 128, 8, 3), 128>>>(l1, l2, l3, ext_w1, ext_b1, h);
    convP_k<8, true, false><<<dim3(18, 8, 3), 128>>>(h, ext_w2, ext_b2, f);

    // projections -> bf16 tensor-core operand layouts
    projT8s_k<<<dim3(AN / 64, 3), 256>>>(f, q_w, q_b, k_w, k_b, QT, KT1, KT3);
    projV_k<<<dim3(AN / 64, 2), 256>>>(f, v_w, v_b, V1, V3);

    // both cross attentions, 2-way key split (288 CTAs), pipelined
    attn_mma_k<<<dim3(AN / 128, 2, 2), 256>>>(QT, KT1, V1, KT3, V3, oP, rsP);

    // combine partials + fuse (padded), then fusion convs
    comb_fuse_k<<<dim3(AN / 256, FD), 256>>>(oP, rsP, f2, fus);
    convP_k<8, true, true><<<dim3(18, 8, 1), 128>>>(fus, fus_w1, fus_b1, fh);
    convF2_k<<<AN / 128, 128>>>(fh, fus_w2, fus_b2, out);
}

// round 8
// speedup vs baseline: 1.0002x; 1.0002x over previous
#include <cuda_runtime.h>
#include <cuda_bf16.h>
#include <cstdint>

#define AN 9216      // N = 96*96
#define HH 96
#define WW 96
#define FD 64
#define PW 98        // padded width
#define PAN (PW*PW)  // padded plane = 9604

// ---------------- scratch (device globals; no allocation allowed) ------------
__device__ float g_h [3*FD*PAN];          // padded extractor hidden
__device__ float g_f [3*FD*AN];           // features f1,f2,f3 (unpadded)
__device__ __nv_bfloat16 g_QT [AN*8];     // [n][8] (pre-scaled by log2e)
__device__ __nv_bfloat16 g_KT1[AN*8];
__device__ __nv_bfloat16 g_KT3[AN*8];
__device__ __nv_bfloat16 g_V1 [AN*FD];    // [key][64]
__device__ __nv_bfloat16 g_V3 [AN*FD];
__device__ float g_oP [4*FD*AN];          // partial O: [pca*2+half][ch][n]
__device__ float g_rsP[4*AN];             // partial rowsums
__device__ float g_fus[FD*PAN];           // padded
__device__ float g_fh [FD*PAN];           // padded

// ---------------- helpers -----------------------------------------------------
__device__ __forceinline__ uint32_t smem_u32(const void* p) {
    uint32_t a;
    asm("{ .reg .u64 t; cvta.to.shared.u64 t, %1; cvt.u32.u64 %0, t; }" : "=r"(a) : "l"(p));
    return a;
}
__device__ __forceinline__ float ex2f(float x) {
    float y;
    asm("ex2.approx.f32 %0, %1;" : "=f"(y) : "f"(x));
    return y;
}
__device__ __forceinline__ void mma_s8(float c[4], uint32_t a0, uint32_t a1, uint32_t b) {
    asm("mma.sync.aligned.m16n8k8.row.col.f32.bf16.bf16.f32 "
        "{%0,%1,%2,%3},{%4,%5},{%6},{%0,%1,%2,%3};"
        : "+f"(c[0]), "+f"(c[1]), "+f"(c[2]), "+f"(c[3])
        : "r"(a0), "r"(a1), "r"(b));
}
__device__ __forceinline__ void mma_pv(float c[4], const uint32_t a[4], uint32_t b0, uint32_t b1) {
    asm("mma.sync.aligned.m16n8k16.row.col.f32.bf16.bf16.f32 "
        "{%0,%1,%2,%3},{%4,%5,%6,%7},{%8,%9},{%0,%1,%2,%3};"
        : "+f"(c[0]), "+f"(c[1]), "+f"(c[2]), "+f"(c[3])
        : "r"(a[0]), "r"(a[1]), "r"(a[2]), "r"(a[3]), "r"(b0), "r"(b1));
}
__device__ __forceinline__ void ldsm4t(uint32_t r[4], uint32_t addr) {
    asm volatile("ldmatrix.sync.aligned.m8n8.x4.trans.shared.b16 {%0,%1,%2,%3}, [%4];"
                 : "=r"(r[0]), "=r"(r[1]), "=r"(r[2]), "=r"(r[3]) : "r"(addr));
}
__device__ __forceinline__ uint32_t pkbf(float lo, float hi) {
    __nv_bfloat162 h2 = __floats2bfloat162_rn(lo, hi);
    return *reinterpret_cast<uint32_t*>(&h2);
}
__device__ __forceinline__ void cpa16(uint32_t dst, const void* src) {
    asm volatile("cp.async.cg.shared.global [%0], [%1], 16;" :: "r"(dst), "l"(src) : "memory");
}
#define CPA_COMMIT() asm volatile("cp.async.commit_group;" ::: "memory")
#define CPA_WAIT0()  asm volatile("cp.async.wait_group 0;" ::: "memory")

// ---------------- zero the pad rings of padded buffers -----------------------
// 320 channel-planes: h(3*64), fus(64), fh(64). Ring = 388 elems/plane.
__global__ void padzero_k(float* h, float* fus, float* fh) {
    const int b = blockIdx.x;
    float* base = (b < 192) ? (h + (long)b * PAN)
                : (b < 256) ? (fus + (long)(b - 192) * PAN)
                            : (fh + (long)(b - 256) * PAN);
    const int t = threadIdx.x;
    if (t < 98)       base[t] = 0.0f;                       // top row
    else if (t < 196) base[97 * PW + (t - 98)] = 0.0f;      // bottom row
    else if (t < 292) base[(t - 196 + 1) * PW] = 0.0f;      // left col
    else if (t < 388) base[(t - 292 + 1) * PW + 97] = 0.0f; // right col
}

// ---------------- conv 3->64 from raw NCHW input, writes PADDED --------------
template<int CPB>
__global__ void convA_k(const float* __restrict__ in0, const float* __restrict__ in1,
                        const float* __restrict__ in2,
                        const float* __restrict__ w, const float* __restrict__ bias,
                        float* __restrict__ out) {
    __shared__ float ws[CPB * 3 * 9];
    const int oc0 = blockIdx.y * CPB;
    for (int i = threadIdx.x; i < CPB * 3 * 9; i += blockDim.x)
        ws[i] = w[oc0 * 3 * 9 + i];
    __syncthreads();

    const int z = blockIdx.z;
    const float* in = (z == 0) ? in0 : (z == 1) ? in1 : in2;
    float* outp = out + (long)z * FD * PAN;

    const int p = blockIdx.x * blockDim.x + threadIdx.x;
    const int y = p / WW, x = p % WW;

    float acc[CPB];
#pragma unroll
    for (int k = 0; k < CPB; k++) acc[k] = bias[oc0 + k];

#pragma unroll
    for (int c = 0; c < 3; c++) {
        float v[9];
#pragma unroll
        for (int dy = 0; dy < 3; dy++) {
            const int yy = y + dy - 1;
#pragma unroll
            for (int dx = 0; dx < 3; dx++) {
                const int xx = x + dx - 1;
                v[dy * 3 + dx] = (yy >= 0 && yy < HH && xx >= 0 && xx < WW)
                                     ? in[c * AN + yy * WW + xx] : 0.0f;
            }
        }
#pragma unroll
        for (int k = 0; k < CPB; k++) {
            const float* wk = ws + k * 27 + c * 9;
#pragma unroll
            for (int j = 0; j < 9; j++) acc[k] += wk[j] * v[j];
        }
    }
#pragma unroll
    for (int k = 0; k < CPB; k++)
        outp[(oc0 + k) * PAN + (y + 1) * PW + (x + 1)] = fmaxf(acc[k], 0.0f);
}

// ---------------- 64->COUT conv from PADDED input, 2x2 px/thread -------------
// TO_PAD: write padded layout (for chained convs); else raw [c][9216].
template<int CPB, bool RELU, bool TO_PAD>
__global__ __launch_bounds__(128) void convP_k(
    const float* __restrict__ in, const float* __restrict__ w,
    const float* __restrict__ bias, float* __restrict__ out) {
    __shared__ float ws[CPB * FD * 9];
    const int oc0 = blockIdx.y * CPB;
    for (int i = threadIdx.x; i < CPB * FD * 9; i += blockDim.x)
        ws[i] = w[oc0 * FD * 9 + i];
    __syncthreads();

    const float* inz  = in + (long)blockIdx.z * FD * PAN;
    float* outp = out + (long)blockIdx.z * FD * AN;

    const int cell = blockIdx.x * blockDim.x + threadIdx.x;   // 0..2303
    const int cx = cell % 48, cy = cell / 48;
    const int x = 2 * cx, y = 2 * cy;

    float acc[CPB][4];
#pragma unroll
    for (int k = 0; k < CPB; k++) {
        const float b = bias[oc0 + k];
#pragma unroll
        for (int j = 0; j < 4; j++) acc[k][j] = b;
    }

    const float* ip = inz + y * PW + x;   // window rows y..y+3, cols x..x+3 (padded)
    for (int c = 0; c < FD; c++) {
        float v[4][4];
#pragma unroll
        for (int r = 0; r < 4; r++)
#pragma unroll
            for (int s = 0; s < 4; s++)
                v[r][s] = ip[r * PW + s];
        ip += PAN;
#pragma unroll
        for (int k = 0; k < CPB; k++) {
            const float* wk = ws + (k * FD + c) * 9;
#pragma unroll
            for (int r = 0; r < 3; r++)
#pragma unroll
                for (int s = 0; s < 3; s++) {
                    const float wv = wk[r * 3 + s];
                    acc[k][0] += wv * v[r][s];
                    acc[k][1] += wv * v[r][s + 1];
                    acc[k][2] += wv * v[r + 1][s];
                    acc[k][3] += wv * v[r + 1][s + 1];
                }
        }
    }

#pragma unroll
    for (int k = 0; k < CPB; k++)
#pragma unroll
        for (int yy = 0; yy < 2; yy++)
#pragma unroll
            for (int xx = 0; xx < 2; xx++) {
                float r = acc[k][yy * 2 + xx];
                if (RELU) r = fmaxf(r, 0.0f);
                if (TO_PAD)
                    outp[(oc0 + k) * PAN + (y + yy + 1) * PW + (x + xx + 1)] = r;
                else
                    outp[(oc0 + k) * AN + (y + yy) * WW + (x + xx)] = r;
            }
}

// ---------------- final conv 64->3 from PADDED input -------------------------
__global__ void convF2_k(const float* __restrict__ in, const float* __restrict__ w,
                         const float* __restrict__ bias, float* __restrict__ out) {
    __shared__ float ws[3 * FD * 9];
    for (int i = threadIdx.x; i < 3 * FD * 9; i += blockDim.x) ws[i] = w[i];
    __syncthreads();
    const int p = blockIdx.x * blockDim.x + threadIdx.x;
    const int y = p / WW, x = p % WW;
    float acc[3] = {bias[0], bias[1], bias[2]};
    const float* ip = in + y * PW + x;
    for (int c = 0; c < FD; c++) {
        float v[9];
#pragma unroll
        for (int r = 0; r < 3; r++)
#pragma unroll
            for (int s = 0; s < 3; s++) v[r * 3 + s] = ip[r * PW + s];
        ip += PAN;
#pragma unroll
        for (int k = 0; k < 3; k++) {
            const float* wk = ws + (k * FD + c) * 9;
#pragma unroll
            for (int j = 0; j < 9; j++) acc[k] += wk[j] * v[j];
        }
    }
#pragma unroll
    for (int k = 0; k < 3; k++) out[k * AN + p] = acc[k];
}

// -------- Q/K1/K3 projections in one launch, 4 threads per pixel -------------
// z: 0 -> Q(f2) scaled by log2e, 1 -> K(f1), 2 -> K(f3). Output bf16 [n][8].
__global__ __launch_bounds__(256) void projT8s_k(
    const float* __restrict__ f, const float* __restrict__ q_w, const float* __restrict__ q_b,
    const float* __restrict__ k_w, const float* __restrict__ k_b,
    __nv_bfloat16* __restrict__ QT, __nv_bfloat16* __restrict__ KT1,
    __nv_bfloat16* __restrict__ KT3) {
    const int z = blockIdx.y;
    const float* in = (z == 0) ? (f + (long)FD * AN) : (z == 1) ? f : (f + 2L * FD * AN);
    const float* w  = (z == 0) ? q_w : k_w;
    const float* b  = (z == 0) ? q_b : k_b;
    __nv_bfloat16* out = (z == 0) ? QT : (z == 1) ? KT1 : KT3;
    const float scale = (z == 0) ? 1.4426950408889634f : 1.0f;   // fold log2e into Q

    __shared__ float ws[8 * FD];
    for (int i = threadIdx.x; i < 8 * FD; i += 256) ws[i] = w[i] * scale;
    __syncthreads();

    const int tid = threadIdx.x;
    const int p   = tid >> 2;          // pixel within block (0..63)
    const int cc  = tid & 3;           // channel chunk
    const int n   = blockIdx.x * 64 + p;

    float acc[8] = {0, 0, 0, 0, 0, 0, 0, 0};
    const int c0 = cc * 16;
#pragma unroll
    for (int c = c0; c < c0 + 16; c++) {
        const float x = in[c * AN + n];
#pragma unroll
        for (int o = 0; o < 8; o++) acc[o] += ws[o * FD + c] * x;
    }
#pragma unroll
    for (int o = 0; o < 8; o++) {
        acc[o] += __shfl_xor_sync(0xFFFFFFFFu, acc[o], 1);
        acc[o] += __shfl_xor_sync(0xFFFFFFFFu, acc[o], 2);
    }
    if (cc == 0) {
        uint32_t pk[4];
#pragma unroll
        for (int i = 0; i < 4; i++)
            pk[i] = pkbf(acc[2 * i] + b[2 * i] * scale, acc[2 * i + 1] + b[2 * i + 1] * scale);
        reinterpret_cast<uint4*>(out)[n] = make_uint4(pk[0], pk[1], pk[2], pk[3]);
    }
}

// ---------------- V projection as tiled GEMM: 64px x 64out per CTA -----------
__global__ __launch_bounds__(256) void projV_k(
    const float* __restrict__ f, const float* __restrict__ w,
    const float* __restrict__ bias,
    __nv_bfloat16* __restrict__ V1, __nv_bfloat16* __restrict__ V3) {
    __shared__ float sin_[FD][64];
    __shared__ float sw[FD * FD];
    __shared__ float sb[FD];
    const int z = blockIdx.y;
    const float* in = z ? (f + 2L * FD * AN) : f;
    __nv_bfloat16* out = z ? V3 : V1;
    const int n0 = blockIdx.x * 64;
    const int tid = threadIdx.x;

    for (int i = tid; i < FD * FD; i += 256) sw[i] = w[i];
    if (tid < FD) sb[tid] = bias[tid];
#pragma unroll
    for (int p = 0; p < 4; p++) {
        const int idx = tid + p * 256;
        const int c = idx >> 4, q = idx & 15;
        *reinterpret_cast<float4*>(&sin_[c][q * 4]) =
            *reinterpret_cast<const float4*>(in + c * AN + n0 + q * 4);
    }
    __syncthreads();

    const int px = tid & 31;
    const int og = tid >> 5;
    float acc[8][2];
#pragma unroll
    for (int o = 0; o < 8; o++) {
        acc[o][0] = sb[og * 8 + o];
        acc[o][1] = acc[o][0];
    }
#pragma unroll
    for (int c = 0; c < FD; c++) {
        const float x0 = sin_[c][px], x1 = sin_[c][px + 32];
#pragma unroll
        for (int o = 0; o < 8; o++) {
            const float wv = sw[(og * 8 + o) * FD + c];
            acc[o][0] += wv * x0;
            acc[o][1] += wv * x1;
        }
    }
    uint32_t pk0[4], pk1[4];
#pragma unroll
    for (int i = 0; i < 4; i++) {
        pk0[i] = pkbf(acc[2 * i][0], acc[2 * i + 1][0]);
        pk1[i] = pkbf(acc[2 * i][1], acc[2 * i + 1][1]);
    }
    *reinterpret_cast<uint4*>(out + (long)(n0 + px) * FD + og * 8) =
        make_uint4(pk0[0], pk0[1], pk0[2], pk0[3]);
    *reinterpret_cast<uint4*>(out + (long)(n0 + px + 32) * FD + og * 8) =
        make_uint4(pk1[0], pk1[1], pk1[2], pk1[3]);
}

// ---------------- mma.sync flash cross-attention, key-split, pipelined -------
// grid (72, pca, key-half). Double-buffered V tile via cp.async; K fragments
// software-prefetched one chunk ahead. Writes UNNORMALIZED partial O + rowsums.
__global__ __launch_bounds__(256, 2) void attn_mma_k(
    const __nv_bfloat16* __restrict__ qt,
    const __nv_bfloat16* __restrict__ kt1, const __nv_bfloat16* __restrict__ v1,
    const __nv_bfloat16* __restrict__ kt3, const __nv_bfloat16* __restrict__ v3,
    float* __restrict__ oP, float* __restrict__ rsP) {

    __shared__ __align__(128) __nv_bfloat16 sv[2][128 * FD];   // 2 x 16 KB V tiles

    const __nv_bfloat16* kt = blockIdx.y ? kt3 : kt1;
    const __nv_bfloat16* v  = blockIdx.y ? v3  : v1;
    const int part = blockIdx.y * 2 + blockIdx.z;
    float* out = oP  + (long)part * FD * AN;
    float* rso = rsP + part * AN;

    const int tid  = threadIdx.x;
    const int wid  = tid >> 5;
    const int lane = tid & 31;
    const int gid  = lane >> 2;      // row group within fragment
    const int tig  = lane & 3;       // thread-in-group
    const int q0   = blockIdx.x * 128;
    const int qb   = q0 + wid * 16;
    const int t0   = blockIdx.z * 36;

    // Q A-fragments (persist across all key tiles)
    const uint32_t qa0 = *reinterpret_cast<const uint32_t*>(qt + (qb + gid) * 8 + tig * 2);
    const uint32_t qa1 = *reinterpret_cast<const uint32_t*>(qt + (qb + 8 + gid) * 8 + tig * 2);

    float o[8][4];
#pragma unroll
    for (int i = 0; i < 8; i++)
#pragma unroll
        for (int j = 0; j < 4; j++) o[i][j] = 0.0f;
    float rs_lo = 0.0f, rs_hi = 0.0f;

    const uint32_t svb = smem_u32(&sv[0][0]);
    const int lm_m = lane >> 3, lm_r = lane & 7;
    const int lm_krow_off = (lm_m & 1) * 8 + lm_r;   // key row within 16-chunk
    const int lm_c16_off  = lm_m >> 1;               // 16B column offset (0 or 1)

    // cp.async V-tile fill: 1 src ptr + fixed offsets (swizzle is p-invariant)
    const int vkey = tid >> 3, vc16 = tid & 7;
    const uint32_t vdst0 = svb + (uint32_t)(vkey * 128 + ((vc16 ^ (vkey & 7)) << 4));
    const __nv_bfloat16* vsrc = v + (size_t)(t0 * 128 + vkey) * FD + vc16 * 8;

    // prologue: fill buffer 0 with tile t0
    cpa16(vdst0,         vsrc);
    cpa16(vdst0 + 4096,  vsrc + 32 * FD);
    cpa16(vdst0 + 8192,  vsrc + 64 * FD);
    cpa16(vdst0 + 12288, vsrc + 96 * FD);
    CPA_COMMIT();
    vsrc += 128 * FD;
    CPA_WAIT0();
    __syncthreads();

    // rolling K pointer + first chunk's fragments
    const __nv_bfloat16* kp = kt + (size_t)(t0 * 128 + gid) * 8;
    uint32_t kbA = *reinterpret_cast<const uint32_t*>(kp + tig * 2);
    uint32_t kbB = *reinterpret_cast<const uint32_t*>(kp + 64 + tig * 2);
    int cc_left = 36 * 8 - 1;   // chunks remaining after the current one

    for (int t = 0; t < 36; t++) {
        // kick off async copy of next V tile into the other buffer
        if (t < 35) {
            const uint32_t d = vdst0 + (uint32_t)(((t + 1) & 1) * 16384);
            cpa16(d,         vsrc);
            cpa16(d + 4096,  vsrc + 32 * FD);
            cpa16(d + 8192,  vsrc + 64 * FD);
            cpa16(d + 12288, vsrc + 96 * FD);
            CPA_COMMIT();
            vsrc += 128 * FD;
        }
        const uint32_t svread = svb + (uint32_t)((t & 1) * 16384);

#pragma unroll
        for (int j = 0; j < 8; j++) {
            float sA[4] = {0, 0, 0, 0}, sB[4] = {0, 0, 0, 0};
            mma_s8(sA, qa0, qa1, kbA);
            mma_s8(sB, qa0, qa1, kbB);

            // prefetch next chunk's K fragments (covers exp/pv section)
            const __nv_bfloat16* kpn = kp + ((cc_left > 0) ? 128 : 0);
            const uint32_t nA = *reinterpret_cast<const uint32_t*>(kpn + tig * 2);
            const uint32_t nB = *reinterpret_cast<const uint32_t*>(kpn + 64 + tig * 2);
            cc_left--;

#pragma unroll
            for (int i = 0; i < 4; i++) { sA[i] = ex2f(sA[i]); sB[i] = ex2f(sB[i]); }
            rs_lo += (sA[0] + sA[1]) + (sB[0] + sB[1]);
            rs_hi += (sA[2] + sA[3]) + (sB[2] + sB[3]);
            uint32_t pa[4];
            pa[0] = pkbf(sA[0], sA[1]);
            pa[1] = pkbf(sA[2], sA[3]);
            pa[2] = pkbf(sB[0], sB[1]);
            pa[3] = pkbf(sB[2], sB[3]);

            const int krow = j * 16 + lm_krow_off;
            const uint32_t rowb = svread + krow * 128;
#pragma unroll
            for (int np = 0; np < 4; np++) {
                const int c16 = np * 2 + lm_c16_off;
                uint32_t vb[4];
                ldsm4t(vb, rowb + ((c16 ^ (krow & 7)) * 16));
                mma_pv(o[2 * np],     pa, vb[0], vb[1]);
                mma_pv(o[2 * np + 1], pa, vb[2], vb[3]);
            }
            kbA = nA; kbB = nB; kp = kpn;
        }

        if (t < 35) CPA_WAIT0();
        __syncthreads();
    }

    rs_lo += __shfl_xor_sync(0xFFFFFFFFu, rs_lo, 1);
    rs_lo += __shfl_xor_sync(0xFFFFFFFFu, rs_lo, 2);
    rs_hi += __shfl_xor_sync(0xFFFFFFFFu, rs_hi, 1);
    rs_hi += __shfl_xor_sync(0xFFFFFFFFu, rs_hi, 2);

    const int row_lo = qb + gid, row_hi = qb + 8 + gid;
    if (tig == 0) { rso[row_lo] = rs_lo; rso[row_hi] = rs_hi; }
#pragma unroll
    for (int nt = 0; nt < 8; nt++) {
        const int ch = nt * 8 + tig * 2;
        out[ch * AN + row_lo]       = o[nt][0];
        out[(ch + 1) * AN + row_lo] = o[nt][1];
        out[ch * AN + row_hi]       = o[nt][2];
        out[(ch + 1) * AN + row_hi] = o[nt][3];
    }
}

// -------- combine key-split partials + normalize + fuse (writes PADDED) ------
__global__ void comb_fuse_k(const float* __restrict__ oP, const float* __restrict__ rsP,
                            const float* __restrict__ f2, float* __restrict__ out) {
    const int n  = blockIdx.x * blockDim.x + threadIdx.x;
    const int ch = blockIdx.y;
    const long i = (long)ch * AN + n;
    const float inv1 = 1.0f / (rsP[n] + rsP[AN + n]);
    const float inv3 = 1.0f / (rsP[2 * AN + n] + rsP[3 * AN + n]);
    const float al1 = (oP[i] + oP[(long)FD * AN + i]) * inv1;
    const float al3 = (oP[2L * FD * AN + i] + oP[3L * FD * AN + i]) * inv3;
    const int y = n / WW, x = n % WW;
    out[(long)ch * PAN + (y + 1) * PW + (x + 1)] =
        (al1 + al3) * (1.0f / 3.0f) + f2[i];
}

// ---------------- launch ------------------------------------------------------
extern "C" void kernel_launch(void* const* d_in, const int* in_sizes, int n_in,
                              void* d_out, int out_size) {
    const float* l1     = (const float*)d_in[0];
    const float* l2     = (const float*)d_in[1];
    const float* l3     = (const float*)d_in[2];
    const float* ext_w1 = (const float*)d_in[3];
    const float* ext_b1 = (const float*)d_in[4];
    const float* ext_w2 = (const float*)d_in[5];
    const float* ext_b2 = (const float*)d_in[6];
    const float* q_w    = (const float*)d_in[7];
    const float* q_b    = (const float*)d_in[8];
    const float* k_w    = (const float*)d_in[9];
    const float* k_b    = (const float*)d_in[10];
    const float* v_w    = (const float*)d_in[11];
    const float* v_b    = (const float*)d_in[12];
    const float* fus_w1 = (const float*)d_in[13];
    const float* fus_b1 = (const float*)d_in[14];
    const float* fus_w2 = (const float*)d_in[15];
    const float* fus_b2 = (const float*)d_in[16];
    float* out = (float*)d_out;

    float *h, *f, *oP, *rsP, *fus, *fh;
    __nv_bfloat16 *QT, *KT1, *KT3, *V1, *V3;
    cudaGetSymbolAddress((void**)&h,   g_h);
    cudaGetSymbolAddress((void**)&f,   g_f);
    cudaGetSymbolAddress((void**)&QT,  g_QT);
    cudaGetSymbolAddress((void**)&KT1, g_KT1);
    cudaGetSymbolAddress((void**)&KT3, g_KT3);
    cudaGetSymbolAddress((void**)&V1,  g_V1);
    cudaGetSymbolAddress((void**)&V3,  g_V3);
    cudaGetSymbolAddress((void**)&oP,  g_oP);
    cudaGetSymbolAddress((void**)&rsP, g_rsP);
    cudaGetSymbolAddress((void**)&fus, g_fus);
    cudaGetSymbolAddress((void**)&fh,  g_fh);

    float* f2 = f + (long)FD * AN;

    // zero pad rings of padded buffers (idempotent, every call)
    padzero_k<<<320, 512>>>(h, fus, fh);

    // feature extraction
    convA_k<8><<<dim3(AN / 128, 8, 3), 128>>>(l1, l2, l3, ext_w1, ext_b1, h);
    convP_k<8, true, false><<<dim3(18, 8, 3), 128>>>(h, ext_w2, ext_b2, f);

    // projections -> bf16 tensor-core operand layouts
    projT8s_k<<<dim3(AN / 64, 3), 256>>>(f, q_w, q_b, k_w, k_b, QT, KT1, KT3);
    projV_k<<<dim3(AN / 64, 2), 256>>>(f, v_w, v_b, V1, V3);

    // both cross attentions, 2-way key split (288 CTAs), pipelined
    attn_mma_k<<<dim3(AN / 128, 2, 2), 256>>>(QT, KT1, V1, KT3, V3, oP, rsP);

    // combine partials + fuse (padded), then fusion convs
    comb_fuse_k<<<dim3(AN / 256, FD), 256>>>(oP, rsP, f2, fus);
    convP_k<8, true, true><<<dim3(18, 8, 1), 128>>>(fus, fus_w1, fus_b1, fh);
    convF2_k<<<AN / 128, 128>>>(fh, fus_w2, fus_b2, out);
}